// round 3
// baseline (speedup 1.0000x reference)
#include <cuda_runtime.h>
#include <math.h>

// ---------------- problem constants ----------------
#define B_DIM   2048
#define HID     512
#define DIM_OUT 256
#define MAXN    128
#define MID_S   256   // (HID+1)/2
#define MID_K   320   // (MAXN+HID)/2
#define MID_D   384   // (HID+DIM)/2

#define X_SIZE  (2048LL*128*256)           // 67108864
#define N_OFF   X_SIZE
#define MASK_OFF (X_SIZE + 2048LL)

// ---------------- device scratch (no allocation allowed) ----------------
__device__ __align__(16) float g_keys[MAXN * HID];   // keys[k, :]  128x512
__device__ int   g_n[B_DIM];

// ---------------- helpers ----------------
__device__ __forceinline__ float mishf(float x) {
    // accurate path (used in size_pred / key_net)
    float sp = fmaxf(x, 0.f) + log1pf(expf(-fabsf(x)));
    return x * tanhf(sp);
}

__device__ __forceinline__ float mish_fast(float x) {
    // tanh(softplus(x)) = (y^2-1)/(y^2+1), y = 1 + e^x  (exact identity)
    float e = __expf(x);
    float y = 1.f + e;
    float d = fmaf(y, y, 1.f);
    return x - 2.f * x / d;
}

#define FMA2(d, a, b) asm("fma.rn.f32x2 %0, %1, %2, %0;" : "+l"(d) : "l"(a), "l"(b))
#define DUP2(d, a)    asm("mov.b64 %0, {%1, %1};" : "=l"(d) : "f"(a))
#define UNP2(lo, hi, s) asm("mov.b64 {%0, %1}, %2;" : "=f"(lo), "=f"(hi) : "l"(s))

// =====================================================================
// Kernel A: size_pred -> n[b], plus n-float and mask outputs.
// =====================================================================
__global__ __launch_bounds__(256)
void sizepred_kernel(const float* __restrict__ z,
                     const float* __restrict__ W1, const float* __restrict__ b1,
                     const float* __restrict__ g,  const float* __restrict__ be,
                     const float* __restrict__ W2, const float* __restrict__ b2,
                     float* __restrict__ out, int write_n, int write_mask)
{
    __shared__ float zsh[8][HID];
    __shared__ float hsh[8][MID_S];
    __shared__ float smean[8], srstd[8];
    __shared__ int   nsh[8];

    const int b0  = blockIdx.x * 8;
    const int tid = threadIdx.x;

    #pragma unroll
    for (int e = 0; e < 16; ++e) {
        int lin = e * 256 + tid;
        int bb = lin >> 9, i = lin & 511;
        zsh[bb][i] = z[(size_t)(b0 + bb) * HID + i];
    }
    __syncthreads();

    const int j = tid;
    float acc[8];
    {
        float bj = b1[j];
        #pragma unroll
        for (int bb = 0; bb < 8; ++bb) acc[bb] = bj;
    }
    for (int i = 0; i < HID; i += 4) {
        #pragma unroll
        for (int ii = 0; ii < 4; ++ii) {
            float w = W1[(size_t)(i + ii) * MID_S + j];
            #pragma unroll
            for (int bb = 0; bb < 8; ++bb)
                acc[bb] = fmaf(zsh[bb][i + ii], w, acc[bb]);
        }
    }
    #pragma unroll
    for (int bb = 0; bb < 8; ++bb) hsh[bb][j] = acc[bb];
    __syncthreads();

    const int wrow = tid >> 5, lane = tid & 31;
    {
        float s = 0.f, s2 = 0.f;
        for (int jj = lane; jj < MID_S; jj += 32) {
            float v = hsh[wrow][jj];
            s += v; s2 += v * v;
        }
        #pragma unroll
        for (int o = 16; o; o >>= 1) {
            s  += __shfl_xor_sync(0xffffffffu, s,  o);
            s2 += __shfl_xor_sync(0xffffffffu, s2, o);
        }
        if (lane == 0) {
            float m = s * (1.f / MID_S);
            float var = s2 * (1.f / MID_S) - m * m;
            smean[wrow] = m;
            srstd[wrow] = rsqrtf(var + 1e-5f);
        }
    }
    __syncthreads();

    {
        float gj = g[j], bej = be[j], w2j = W2[j];
        #pragma unroll
        for (int bb = 0; bb < 8; ++bb) {
            float v = (acc[bb] - smean[bb]) * srstd[bb] * gj + bej;
            hsh[bb][j] = mishf(v) * w2j;
        }
    }
    __syncthreads();

    {
        float s = 0.f;
        for (int jj = lane; jj < MID_S; jj += 32) s += hsh[wrow][jj];
        #pragma unroll
        for (int o = 16; o; o >>= 1) s += __shfl_xor_sync(0xffffffffu, s, o);
        if (lane == 0) {
            float logit = s + b2[0];
            float nf = fminf(fmaxf(rintf(logit), 0.f), (float)MAXN);
            int ni = (int)nf;
            g_n[b0 + wrow] = ni;
            nsh[wrow] = ni;
            if (write_n) out[N_OFF + b0 + wrow] = nf;
        }
    }
    __syncthreads();

    if (write_mask) {
        #pragma unroll
        for (int e = 0; e < 4; ++e) {
            int lin = e * 256 + tid;
            int bb = lin >> 7, kk = lin & 127;
            out[MASK_OFF + (size_t)(b0 + bb) * MAXN + kk] = (kk < nsh[bb]) ? 1.f : 0.f;
        }
    }
}

// =====================================================================
// Kernel B: keys = mish(ln(kn_W1 + kn_b1)) @ kn_W2 + kn_b2   (pos = I)
// =====================================================================
__global__ __launch_bounds__(512)
void keys_kernel(const float* __restrict__ W1, const float* __restrict__ b1,
                 const float* __restrict__ g,  const float* __restrict__ be,
                 const float* __restrict__ W2, const float* __restrict__ b2)
{
    __shared__ float hs[MID_K];
    __shared__ float warp_s[16], warp_s2[16];
    __shared__ float st_mean, st_rstd;

    const int k = blockIdx.x;
    const int tid = threadIdx.x;
    const bool act = tid < MID_K;

    float v = 0.f;
    if (act) v = W1[(size_t)k * MID_K + tid] + b1[tid];

    float s = v, s2 = v * v;
    #pragma unroll
    for (int o = 16; o; o >>= 1) {
        s  += __shfl_xor_sync(0xffffffffu, s,  o);
        s2 += __shfl_xor_sync(0xffffffffu, s2, o);
    }
    const int wid = tid >> 5, lane = tid & 31;
    if (lane == 0) { warp_s[wid] = s; warp_s2[wid] = s2; }
    __syncthreads();
    if (wid == 0) {
        float ps  = (lane < 16) ? warp_s[lane]  : 0.f;
        float ps2 = (lane < 16) ? warp_s2[lane] : 0.f;
        #pragma unroll
        for (int o = 8; o; o >>= 1) {
            ps  += __shfl_xor_sync(0xffffffffu, ps,  o);
            ps2 += __shfl_xor_sync(0xffffffffu, ps2, o);
        }
        if (lane == 0) {
            float m = ps * (1.f / MID_K);
            float var = ps2 * (1.f / MID_K) - m * m;
            st_mean = m;
            st_rstd = rsqrtf(var + 1e-5f);
        }
    }
    __syncthreads();

    if (act)
        hs[tid] = mishf((v - st_mean) * st_rstd * g[tid] + be[tid]);
    __syncthreads();

    const int o = tid;
    float acc = b2[o];
    for (int jj = 0; jj < MID_K; jj += 4) {
        #pragma unroll
        for (int u = 0; u < 4; ++u)
            acc = fmaf(hs[jj + u], W2[(size_t)(jj + u) * HID + o], acc);
    }
    g_keys[(size_t)k * HID + o] = acc;
}

// =====================================================================
// Kernel C: decoder. One block per batch row b, 256 threads = 8 warps.
// Two 64-row groups per b (skip group if r0 >= n, zero-fill only).
// A-tile [64][516] fp32 aliased with H-tile [64][396]; weights double-
// buffered in 8-row chunks; all inner math in packed fma.rn.f32x2.
// =====================================================================
#define PAD_A 516
#define PAD_H 396
#define SM_WB 33024                 // 64*516
#define SM_ZS (SM_WB + 6144)        // 2 x 3072-float weight buffers
#define DEC_SMEM_FLOATS (SM_ZS + 512)
#define DEC_SMEM_BYTES (DEC_SMEM_FLOATS * 4)

__global__ __launch_bounds__(256)
void decoder_kernel(const float* __restrict__ z,
                    const float* __restrict__ W1, const float* __restrict__ b1c,
                    const float* __restrict__ W2, const float* __restrict__ b2c,
                    float* __restrict__ out)
{
    extern __shared__ float sm[];
    float* at = sm;           // [64][516] (GEMM1 A, transposed-free row-major)
    float* ht = sm;           // [64][396] alias (GEMM2 A)
    float* wb = sm + SM_WB;   // 2 x 3072
    float* zs = sm + SM_ZS;   // [512]

    const int b   = blockIdx.x;
    const int tid = threadIdx.x;
    const int ty  = tid >> 5;   // 0..7   -> rows ty*8 .. ty*8+7
    const int tx  = tid & 31;   // 0..31  -> cols s*128 + tx*4 ..

    const int n = g_n[b];

    #pragma unroll
    for (int e = 0; e < 2; ++e) zs[e * 256 + tid] = z[(size_t)b * HID + e * 256 + tid];

    float* outb = out + (size_t)b * MAXN * DIM_OUT;
    const float4* W1v = reinterpret_cast<const float4*>(W1);
    const float4* W2v = reinterpret_cast<const float4*>(W2);
    const float4* b1v = reinterpret_cast<const float4*>(b1c);
    const float4* b2v = reinterpret_cast<const float4*>(b2c);
    const float4* k4  = reinterpret_cast<const float4*>(g_keys);
    const float4* z4  = reinterpret_cast<const float4*>(zs);

    for (int gidx = 0; gidx < 2; ++gidx) {
        const int r0 = gidx * 64;
        if (r0 >= n) {
            float4 zz = make_float4(0.f, 0.f, 0.f, 0.f);
            float4* o4 = reinterpret_cast<float4*>(outb + (size_t)r0 * DIM_OUT);
            #pragma unroll
            for (int e = 0; e < 16; ++e) o4[e * 256 + tid] = zz;
            continue;
        }

        __syncthreads();   // zs ready / previous group's ht reads done

        // ---- build A[r][q] = keys[r0+r][q] * z[q]  (row-major, pad 516) ----
        #pragma unroll
        for (int e = 0; e < 32; ++e) {
            int lin = e * 256 + tid;        // 0..8191
            int r  = lin >> 7;              // 0..63
            int qq = lin & 127;             // float4 index
            float4 kv = k4[(size_t)(r0 + r) * 128 + qq];
            float4 zv = z4[qq];
            float4 av;
            av.x = kv.x * zv.x; av.y = kv.y * zv.y;
            av.z = kv.z * zv.z; av.w = kv.w * zv.w;
            *reinterpret_cast<float4*>(&at[r * PAD_A + qq * 4]) = av;
        }
        __syncthreads();

        // ================= GEMM1: H[64,384] = A[64,512] @ W1 =================
        unsigned long long acc[8][6];
        #pragma unroll
        for (int rr = 0; rr < 8; ++rr)
            #pragma unroll
            for (int cc = 0; cc < 6; ++cc) acc[rr][cc] = 0ull;

        float4 wreg[3];
        #pragma unroll
        for (int e = 0; e < 3; ++e) wreg[e] = W1v[e * 256 + tid];

        int p = 0;
        for (int qb = 0; qb < HID; qb += 8) {
            float4* dst = reinterpret_cast<float4*>(wb + p * 3072);
            #pragma unroll
            for (int e = 0; e < 3; ++e) dst[e * 256 + tid] = wreg[e];
            __syncthreads();
            if (qb + 8 < HID) {
                const float4* src = W1v + (size_t)(qb + 8) * 96;
                #pragma unroll
                for (int e = 0; e < 3; ++e) wreg[e] = src[e * 256 + tid];
            }
            const float* wbuf = wb + p * 3072;

            #pragma unroll
            for (int q = 0; q < 8; ++q) {
                unsigned long long ad[8];
                #pragma unroll
                for (int rr = 0; rr < 8; ++rr) {
                    float av = at[(ty * 8 + rr) * PAD_A + qb + q];
                    DUP2(ad[rr], av);
                }
                #pragma unroll
                for (int s = 0; s < 3; ++s) {
                    ulonglong2 w2 = *reinterpret_cast<const ulonglong2*>(
                        &wbuf[q * 384 + s * 128 + (tx << 2)]);
                    #pragma unroll
                    for (int rr = 0; rr < 8; ++rr) {
                        FMA2(acc[rr][2 * s],     ad[rr], w2.x);
                        FMA2(acc[rr][2 * s + 1], ad[rr], w2.y);
                    }
                }
            }
            p ^= 1;
        }
        __syncthreads();   // all A reads done, wb reads done

        // ---- epilogue 1: +b1, mish, store H row-major (pad 396) ----
        #pragma unroll
        for (int s = 0; s < 3; ++s) {
            float4 bb = __ldg(&b1v[s * 32 + tx]);
            #pragma unroll
            for (int rr = 0; rr < 8; ++rr) {
                float v0, v1, v2, v3;
                UNP2(v0, v1, acc[rr][2 * s]);
                UNP2(v2, v3, acc[rr][2 * s + 1]);
                float4 hv;
                hv.x = mish_fast(v0 + bb.x);
                hv.y = mish_fast(v1 + bb.y);
                hv.z = mish_fast(v2 + bb.z);
                hv.w = mish_fast(v3 + bb.w);
                *reinterpret_cast<float4*>(
                    &ht[(ty * 8 + rr) * PAD_H + s * 128 + (tx << 2)]) = hv;
            }
        }
        __syncthreads();

        // ================= GEMM2: X[64,256] = H[64,384] @ W2 =================
        unsigned long long acc2[8][4];
        #pragma unroll
        for (int rr = 0; rr < 8; ++rr)
            #pragma unroll
            for (int cc = 0; cc < 4; ++cc) acc2[rr][cc] = 0ull;

        float4 wreg2[2];
        #pragma unroll
        for (int e = 0; e < 2; ++e) wreg2[e] = W2v[e * 256 + tid];

        p = 0;
        for (int qb = 0; qb < MID_D; qb += 8) {
            float4* dst = reinterpret_cast<float4*>(wb + p * 3072);
            #pragma unroll
            for (int e = 0; e < 2; ++e) dst[e * 256 + tid] = wreg2[e];
            __syncthreads();
            if (qb + 8 < MID_D) {
                const float4* src = W2v + (size_t)(qb + 8) * 64;
                #pragma unroll
                for (int e = 0; e < 2; ++e) wreg2[e] = src[e * 256 + tid];
            }
            const float* wbuf = wb + p * 3072;

            #pragma unroll
            for (int q = 0; q < 8; ++q) {
                unsigned long long ad[8];
                #pragma unroll
                for (int rr = 0; rr < 8; ++rr) {
                    float av = ht[(ty * 8 + rr) * PAD_H + qb + q];
                    DUP2(ad[rr], av);
                }
                #pragma unroll
                for (int s = 0; s < 2; ++s) {
                    ulonglong2 w2 = *reinterpret_cast<const ulonglong2*>(
                        &wbuf[q * 256 + s * 128 + (tx << 2)]);
                    #pragma unroll
                    for (int rr = 0; rr < 8; ++rr) {
                        FMA2(acc2[rr][2 * s],     ad[rr], w2.x);
                        FMA2(acc2[rr][2 * s + 1], ad[rr], w2.y);
                    }
                }
            }
            p ^= 1;
        }

        // ---- epilogue 2: +b2, mask rows >= n, write float4 ----
        #pragma unroll
        for (int s = 0; s < 2; ++s) {
            float4 bb = __ldg(&b2v[s * 32 + tx]);
            #pragma unroll
            for (int rr = 0; rr < 8; ++rr) {
                int r = r0 + ty * 8 + rr;
                bool valid = r < n;
                float v0, v1, v2, v3;
                UNP2(v0, v1, acc2[rr][2 * s]);
                UNP2(v2, v3, acc2[rr][2 * s + 1]);
                float4 o;
                o.x = valid ? v0 + bb.x : 0.f;
                o.y = valid ? v1 + bb.y : 0.f;
                o.z = valid ? v2 + bb.z : 0.f;
                o.w = valid ? v3 + bb.w : 0.f;
                *reinterpret_cast<float4*>(
                    &outb[(size_t)r * DIM_OUT + s * 128 + (tx << 2)]) = o;
            }
        }
        __syncthreads();   // wb/ht reads done before next group reuses smem
    }
}

// =====================================================================
// launch
// =====================================================================
extern "C" void kernel_launch(void* const* d_in, const int* in_sizes, int n_in,
                              void* d_out, int out_size)
{
    const float* z     = (const float*)d_in[0];
    const float* sp_W1 = (const float*)d_in[1];
    const float* sp_b1 = (const float*)d_in[2];
    const float* sp_g  = (const float*)d_in[3];
    const float* sp_be = (const float*)d_in[4];
    const float* sp_W2 = (const float*)d_in[5];
    const float* sp_b2 = (const float*)d_in[6];
    const float* kn_W1 = (const float*)d_in[7];
    const float* kn_b1 = (const float*)d_in[8];
    const float* kn_g  = (const float*)d_in[9];
    const float* kn_be = (const float*)d_in[10];
    const float* kn_W2 = (const float*)d_in[11];
    const float* kn_b2 = (const float*)d_in[12];
    const float* de_W1 = (const float*)d_in[13];
    const float* de_b1 = (const float*)d_in[14];
    const float* de_W2 = (const float*)d_in[15];
    const float* de_b2 = (const float*)d_in[16];
    float* out = (float*)d_out;

    long long osz = (long long)out_size;
    int write_n    = (osz >= X_SIZE + B_DIM) ? 1 : 0;
    int write_mask = (osz >= X_SIZE + B_DIM + (long long)B_DIM * MAXN) ? 1 : 0;

    cudaFuncSetAttribute(decoder_kernel,
                         cudaFuncAttributeMaxDynamicSharedMemorySize,
                         DEC_SMEM_BYTES);

    sizepred_kernel<<<256, 256>>>(z, sp_W1, sp_b1, sp_g, sp_be, sp_W2, sp_b2,
                                  out, write_n, write_mask);
    keys_kernel<<<128, 512>>>(kn_W1, kn_b1, kn_g, kn_be, kn_W2, kn_b2);
    decoder_kernel<<<B_DIM, 256, DEC_SMEM_BYTES>>>(z, de_W1, de_b1, de_W2, de_b2, out);
}

// round 5
// speedup vs baseline: 2.2265x; 2.2265x over previous
#include <cuda_runtime.h>
#include <math.h>
#include <cstdint>

#define B_DIM   2048
#define HID     512
#define DIM_OUT 256
#define MAXN    128
#define MID_S   256
#define MID_K   320
#define MID_D   384

#define X_SIZE  (2048LL*128*256)
#define N_OFF   X_SIZE
#define MASK_OFF (X_SIZE + 2048LL)

__device__ __align__(16) float g_keys[MAXN * HID];
__device__ int   g_n[B_DIM];
// W1^T in k16 chunks: [32 chunks][384 n][18 (16 k + 2 pad)] tf32
__device__ __align__(16) float g_W1c[32 * 384 * 18];
// W2^T in k16 chunks: [24 chunks][256 n][18] tf32
__device__ __align__(16) float g_W2c[24 * 256 * 18];

__device__ __forceinline__ float mishf(float x) {
    float sp = fmaxf(x, 0.f) + log1pf(expf(-fabsf(x)));
    return x * tanhf(sp);
}
__device__ __forceinline__ float mish_fast(float x) {
    float e = __expf(x);
    float y = 1.f + e;
    float d = fmaf(y, y, 1.f);
    return x - 2.f * x * __frcp_rn(d);
}
__device__ __forceinline__ float tf32r(float x) {
    uint32_t u;
    asm("cvt.rna.tf32.f32 %0, %1;" : "=r"(u) : "f"(x));
    return __uint_as_float(u);
}
__device__ __forceinline__ void cp16(uint32_t dst, const void* src) {
    asm volatile("cp.async.cg.shared.global [%0], [%1], 16;" :: "r"(dst), "l"(src));
}
#define CP_COMMIT() asm volatile("cp.async.commit_group;" ::: "memory")
#define CP_WAIT1()  asm volatile("cp.async.wait_group 1;" ::: "memory")
#define CP_WAIT0()  asm volatile("cp.async.wait_group 0;" ::: "memory")

__device__ __forceinline__ void mma_tf32(float* c, const uint32_t* a,
                                         uint32_t b0, uint32_t b1) {
    asm volatile(
        "mma.sync.aligned.m16n8k8.row.col.f32.tf32.tf32.f32 "
        "{%0,%1,%2,%3}, {%4,%5,%6,%7}, {%8,%9}, {%0,%1,%2,%3};"
        : "+f"(c[0]), "+f"(c[1]), "+f"(c[2]), "+f"(c[3])
        : "r"(a[0]), "r"(a[1]), "r"(a[2]), "r"(a[3]), "r"(b0), "r"(b1));
}
__device__ __forceinline__ uint32_t smem_u32(const void* p) {
    uint32_t a;
    asm("{ .reg .u64 t; cvta.to.shared.u64 t, %1; cvt.u32.u64 %0, t; }" : "=r"(a) : "l"(p));
    return a;
}

// ===================== Kernel A: size_pred (4 rows/block) =====================
__global__ __launch_bounds__(256)
void sizepred_kernel(const float* __restrict__ z,
                     const float* __restrict__ W1, const float* __restrict__ b1,
                     const float* __restrict__ g,  const float* __restrict__ be,
                     const float* __restrict__ W2, const float* __restrict__ b2,
                     float* __restrict__ out, int write_n, int write_mask)
{
    __shared__ float zsh[4][HID];
    __shared__ float hsh[4][MID_S];
    __shared__ float smean[4], srstd[4];
    __shared__ int   nsh[4];
    const int b0  = blockIdx.x * 4;
    const int tid = threadIdx.x;

    #pragma unroll
    for (int e = 0; e < 8; ++e) {
        int lin = e * 256 + tid;
        int bb = lin >> 9, i = lin & 511;
        zsh[bb][i] = z[(size_t)(b0 + bb) * HID + i];
    }
    __syncthreads();

    const int j = tid;
    float acc[4];
    {
        float bj = b1[j];
        #pragma unroll
        for (int bb = 0; bb < 4; ++bb) acc[bb] = bj;
    }
    for (int i = 0; i < HID; i += 4) {
        #pragma unroll
        for (int ii = 0; ii < 4; ++ii) {
            float w = W1[(size_t)(i + ii) * MID_S + j];
            #pragma unroll
            for (int bb = 0; bb < 4; ++bb)
                acc[bb] = fmaf(zsh[bb][i + ii], w, acc[bb]);
        }
    }
    #pragma unroll
    for (int bb = 0; bb < 4; ++bb) hsh[bb][j] = acc[bb];
    __syncthreads();

    const int wrow = (tid >> 5) & 3, lane = tid & 31;
    {
        float s = 0.f, s2 = 0.f;
        for (int jj = lane; jj < MID_S; jj += 32) {
            float v = hsh[wrow][jj];
            s += v; s2 += v * v;
        }
        #pragma unroll
        for (int o = 16; o; o >>= 1) {
            s  += __shfl_xor_sync(0xffffffffu, s,  o);
            s2 += __shfl_xor_sync(0xffffffffu, s2, o);
        }
        if (lane == 0) {
            float m = s * (1.f / MID_S);
            float var = s2 * (1.f / MID_S) - m * m;
            smean[wrow] = m;
            srstd[wrow] = rsqrtf(var + 1e-5f);
        }
    }
    __syncthreads();

    {
        float gj = g[j], bej = be[j], w2j = W2[j];
        #pragma unroll
        for (int bb = 0; bb < 4; ++bb) {
            float v = (acc[bb] - smean[bb]) * srstd[bb] * gj + bej;
            hsh[bb][j] = mishf(v) * w2j;
        }
    }
    __syncthreads();

    {
        float s = 0.f;
        for (int jj = lane; jj < MID_S; jj += 32) s += hsh[wrow][jj];
        #pragma unroll
        for (int o = 16; o; o >>= 1) s += __shfl_xor_sync(0xffffffffu, s, o);
        if (lane == 0) {
            float logit = s + b2[0];
            float nf = fminf(fmaxf(rintf(logit), 0.f), (float)MAXN);
            int ni = (int)nf;
            g_n[b0 + wrow] = ni;
            nsh[wrow] = ni;
            if (write_n) out[N_OFF + b0 + wrow] = nf;
        }
    }
    __syncthreads();

    if (write_mask) {
        #pragma unroll
        for (int e = 0; e < 2; ++e) {
            int lin = e * 256 + tid;
            int bb = lin >> 7, kk = lin & 127;
            out[MASK_OFF + (size_t)(b0 + bb) * MAXN + kk] = (kk < nsh[bb]) ? 1.f : 0.f;
        }
    }
}

// ===================== Kernel B: keys =====================
__global__ __launch_bounds__(512)
void keys_kernel(const float* __restrict__ W1, const float* __restrict__ b1,
                 const float* __restrict__ g,  const float* __restrict__ be,
                 const float* __restrict__ W2, const float* __restrict__ b2)
{
    __shared__ float hs[MID_K];
    __shared__ float warp_s[16], warp_s2[16];
    __shared__ float st_mean, st_rstd;
    const int k = blockIdx.x;
    const int tid = threadIdx.x;
    const bool act = tid < MID_K;
    float v = 0.f;
    if (act) v = W1[(size_t)k * MID_K + tid] + b1[tid];
    float s = v, s2 = v * v;
    #pragma unroll
    for (int o = 16; o; o >>= 1) {
        s  += __shfl_xor_sync(0xffffffffu, s,  o);
        s2 += __shfl_xor_sync(0xffffffffu, s2, o);
    }
    const int wid = tid >> 5, lane = tid & 31;
    if (lane == 0) { warp_s[wid] = s; warp_s2[wid] = s2; }
    __syncthreads();
    if (wid == 0) {
        float ps  = (lane < 16) ? warp_s[lane]  : 0.f;
        float ps2 = (lane < 16) ? warp_s2[lane] : 0.f;
        #pragma unroll
        for (int o = 8; o; o >>= 1) {
            ps  += __shfl_xor_sync(0xffffffffu, ps,  o);
            ps2 += __shfl_xor_sync(0xffffffffu, ps2, o);
        }
        if (lane == 0) {
            float m = ps * (1.f / MID_K);
            float var = ps2 * (1.f / MID_K) - m * m;
            st_mean = m;
            st_rstd = rsqrtf(var + 1e-5f);
        }
    }
    __syncthreads();
    if (act) hs[tid] = mishf((v - st_mean) * st_rstd * g[tid] + be[tid]);
    __syncthreads();
    const int o = tid;
    float acc = b2[o];
    for (int jj = 0; jj < MID_K; jj += 4) {
        #pragma unroll
        for (int u = 0; u < 4; ++u)
            acc = fmaf(hs[jj + u], W2[(size_t)(jj + u) * HID + o], acc);
    }
    g_keys[(size_t)k * HID + o] = acc;
}

// ===================== Prep: transposed tf32 weight chunk images =====================
#define W1C_TOTAL (32 * 384 * 18)   // 221184
#define W2C_TOTAL (24 * 256 * 18)   // 110592
__global__ __launch_bounds__(256)
void prep_kernel(const float* __restrict__ W1, const float* __restrict__ W2)
{
    int id = blockIdx.x * 256 + threadIdx.x;
    if (id < W1C_TOTAL) {
        int kc = id / 6912, rem = id % 6912;
        int nn = rem / 18, kk = rem % 18;
        float v = (kk < 16) ? W1[(size_t)(kc * 16 + kk) * MID_D + nn] : 0.f;
        g_W1c[id] = tf32r(v);
    } else if (id < W1C_TOTAL + W2C_TOTAL) {
        int t = id - W1C_TOTAL;
        int kc = t / 4608, rem = t % 4608;
        int nn = rem / 18, kk = rem % 18;
        float v = (kk < 16) ? W2[(size_t)(kc * 16 + kk) * DIM_OUT + nn] : 0.f;
        g_W2c[t] = tf32r(v);
    }
}

// ===================== Kernel C: mma.sync tf32 decoder =====================
#define A_STRIDE 516
#define H_STRIDE 388
#define OFF_A 0
#define OFF_W 132096        // 64*516*4
#define W1_CH_BYTES 27648   // 6912*4
#define W2_CH_BYTES 18432   // 4608*4
#define OFF_Z 187392        // OFF_W + 2*27648
#define DEC_SMEM_BYTES 189440

__global__ __launch_bounds__(256, 1)
void decoder_kernel(const float* __restrict__ z,
                    const float* __restrict__ b1c,
                    const float* __restrict__ b2c,
                    float* __restrict__ out)
{
    extern __shared__ char sm[];
    float* As = (float*)(sm + OFF_A);
    float* Hs = (float*)(sm + OFF_A);
    float* zs = (float*)(sm + OFF_Z);
    const uint32_t smb = smem_u32(sm);

    const int b    = blockIdx.x;
    const int tid  = threadIdx.x;
    const int wid  = tid >> 5, lane = tid & 31;
    const int wr   = wid >> 2;          // 0..1 warp row (32 rows each)
    const int wc   = wid & 3;           // 0..3 warp col
    const int tg   = lane >> 2;         // 0..7
    const int tk   = lane & 3;          // 0..3

    zs[tid] = z[(size_t)b * HID + tid];
    zs[256 + tid] = z[(size_t)b * HID + 256 + tid];
    __syncthreads();

    const int n = g_n[b];
    float* outb = out + (size_t)b * MAXN * DIM_OUT;
    const float4* K4 = (const float4*)g_keys;
    const float4* Z4 = (const float4*)zs;
    const float4* W1c4 = (const float4*)g_W1c;
    const float4* W2c4 = (const float4*)g_W2c;

    for (int gidx = 0; gidx < 2; ++gidx) {
        const int r0 = gidx * 64;
        if (r0 >= n) {
            float4 zz = make_float4(0.f, 0.f, 0.f, 0.f);
            float4* o4 = (float4*)(outb + (size_t)r0 * DIM_OUT);
            #pragma unroll
            for (int e = 0; e < 16; ++e) o4[e * 256 + tid] = zz;
            continue;
        }

        // prefetch W1 chunk 0 (buf0 is free here)
        {
            const float4* src = W1c4 + (size_t)0 * 1728;
            uint32_t dst = smb + OFF_W;
            #pragma unroll
            for (int e = 0; e < 6; ++e) cp16(dst + (e * 256 + tid) * 16, src + e * 256 + tid);
            if (tid < 192) cp16(dst + (1536 + tid) * 16, src + 1536 + tid);
            CP_COMMIT();
        }

        // ---- build A[r][k] = tf32(keys[r0+r][k] * z[k]) ----
        #pragma unroll
        for (int e = 0; e < 32; ++e) {
            int idx = e * 256 + tid;        // 0..8191
            int r = idx >> 7, q = idx & 127;
            float4 kv = K4[(size_t)(r0 + r) * 128 + q];
            float4 zv = Z4[q];
            float4 av;
            av.x = tf32r(kv.x * zv.x);
            av.y = tf32r(kv.y * zv.y);
            av.z = tf32r(kv.z * zv.z);
            av.w = tf32r(kv.w * zv.w);
            *(float4*)(As + r * A_STRIDE + q * 4) = av;
        }

        // ================= GEMM1: [64,512] @ W1 -> [64,384] =================
        float c1[2][12][4];
        #pragma unroll
        for (int i = 0; i < 2; ++i)
            #pragma unroll
            for (int jj = 0; jj < 12; ++jj)
                #pragma unroll
                for (int u = 0; u < 4; ++u) c1[i][jj][u] = 0.f;

        for (int kc = 0; kc < 32; ++kc) {
            __syncthreads();                       // prev compute done
            if (kc + 1 < 32) {
                const float4* src = W1c4 + (size_t)(kc + 1) * 1728;
                uint32_t dst = smb + OFF_W + ((kc + 1) & 1) * W1_CH_BYTES;
                #pragma unroll
                for (int e = 0; e < 6; ++e) cp16(dst + (e * 256 + tid) * 16, src + e * 256 + tid);
                if (tid < 192) cp16(dst + (1536 + tid) * 16, src + 1536 + tid);
                CP_COMMIT();
                CP_WAIT1();
            } else {
                CP_WAIT0();
            }
            __syncthreads();                       // buf visible

            const float* Ws = (const float*)(sm + OFF_W + (kc & 1) * W1_CH_BYTES);
            #pragma unroll
            for (int ks = 0; ks < 2; ++ks) {
                const int k0 = kc * 16 + ks * 8;
                uint32_t a[2][4];
                #pragma unroll
                for (int i = 0; i < 2; ++i) {
                    const float* Ar = As + (wr * 32 + i * 16 + tg) * A_STRIDE + k0 + tk;
                    a[i][0] = __float_as_uint(Ar[0]);
                    a[i][1] = __float_as_uint(Ar[8 * A_STRIDE]);
                    a[i][2] = __float_as_uint(Ar[4]);
                    a[i][3] = __float_as_uint(Ar[8 * A_STRIDE + 4]);
                }
                const float* Wp = Ws + (wc * 96 + tg) * 18 + ks * 8 + tk;
                #pragma unroll
                for (int jj = 0; jj < 12; ++jj) {
                    uint32_t b0 = __float_as_uint(Wp[jj * 144]);       // 8*18
                    uint32_t b1 = __float_as_uint(Wp[jj * 144 + 4]);
                    mma_tf32(c1[0][jj], a[0], b0, b1);
                    mma_tf32(c1[1][jj], a[1], b0, b1);
                }
            }
        }
        __syncthreads();   // all A reads done -> region becomes H; W buf0 free

        // prefetch W2 chunk 0 into buf0 (overlap with epilogue math)
        {
            const float4* src = W2c4;
            uint32_t dst = smb + OFF_W;
            #pragma unroll
            for (int e = 0; e < 4; ++e) cp16(dst + (e * 256 + tid) * 16, src + e * 256 + tid);
            if (tid < 128) cp16(dst + (1024 + tid) * 16, src + 1024 + tid);
            CP_COMMIT();
        }

        // ---- epilogue 1: +b1, mish, tf32, store H ----
        #pragma unroll
        for (int jj = 0; jj < 12; ++jj) {
            int col = wc * 96 + jj * 8 + 2 * tk;
            float bx = __ldg(b1c + col), by = __ldg(b1c + col + 1);
            #pragma unroll
            for (int i = 0; i < 2; ++i) {
                int row = wr * 32 + i * 16 + tg;
                float2 v0, v1;
                v0.x = tf32r(mish_fast(c1[i][jj][0] + bx));
                v0.y = tf32r(mish_fast(c1[i][jj][1] + by));
                v1.x = tf32r(mish_fast(c1[i][jj][2] + bx));
                v1.y = tf32r(mish_fast(c1[i][jj][3] + by));
                *(float2*)(Hs + row * H_STRIDE + col) = v0;
                *(float2*)(Hs + (row + 8) * H_STRIDE + col) = v1;
            }
        }

        // ================= GEMM2: [64,384] @ W2 -> [64,256] =================
        float c2[2][8][4];
        #pragma unroll
        for (int i = 0; i < 2; ++i)
            #pragma unroll
            for (int jj = 0; jj < 8; ++jj)
                #pragma unroll
                for (int u = 0; u < 4; ++u) c2[i][jj][u] = 0.f;

        for (int kc = 0; kc < 24; ++kc) {
            __syncthreads();
            if (kc + 1 < 24) {
                const float4* src = W2c4 + (size_t)(kc + 1) * 1152;
                uint32_t dst = smb + OFF_W + ((kc + 1) & 1) * W2_CH_BYTES;
                #pragma unroll
                for (int e = 0; e < 4; ++e) cp16(dst + (e * 256 + tid) * 16, src + e * 256 + tid);
                if (tid < 128) cp16(dst + (1024 + tid) * 16, src + 1024 + tid);
                CP_COMMIT();
                CP_WAIT1();
            } else {
                CP_WAIT0();
            }
            __syncthreads();

            const float* Ws = (const float*)(sm + OFF_W + (kc & 1) * W2_CH_BYTES);
            #pragma unroll
            for (int ks = 0; ks < 2; ++ks) {
                const int k0 = kc * 16 + ks * 8;
                uint32_t a[2][4];
                #pragma unroll
                for (int i = 0; i < 2; ++i) {
                    const float* Hr = Hs + (wr * 32 + i * 16 + tg) * H_STRIDE + k0 + tk;
                    a[i][0] = __float_as_uint(Hr[0]);
                    a[i][1] = __float_as_uint(Hr[8 * H_STRIDE]);
                    a[i][2] = __float_as_uint(Hr[4]);
                    a[i][3] = __float_as_uint(Hr[8 * H_STRIDE + 4]);
                }
                const float* Wp = Ws + (wc * 64 + tg) * 18 + ks * 8 + tk;
                #pragma unroll
                for (int jj = 0; jj < 8; ++jj) {
                    uint32_t b0 = __float_as_uint(Wp[jj * 144]);
                    uint32_t b1 = __float_as_uint(Wp[jj * 144 + 4]);
                    mma_tf32(c2[0][jj], a[0], b0, b1);
                    mma_tf32(c2[1][jj], a[1], b0, b1);
                }
            }
        }

        // ---- output: +b2, mask, store ----
        #pragma unroll
        for (int jj = 0; jj < 8; ++jj) {
            int col = wc * 64 + jj * 8 + 2 * tk;
            float bx = __ldg(b2c + col), by = __ldg(b2c + col + 1);
            #pragma unroll
            for (int i = 0; i < 2; ++i) {
                int row = r0 + wr * 32 + i * 16 + tg;
                float2 o0, o1;
                bool v0 = row < n, v1 = (row + 8) < n;
                o0.x = v0 ? c2[i][jj][0] + bx : 0.f;
                o0.y = v0 ? c2[i][jj][1] + by : 0.f;
                o1.x = v1 ? c2[i][jj][2] + bx : 0.f;
                o1.y = v1 ? c2[i][jj][3] + by : 0.f;
                *(float2*)(outb + (size_t)row * DIM_OUT + col) = o0;
                *(float2*)(outb + (size_t)(row + 8) * DIM_OUT + col) = o1;
            }
        }
        __syncthreads();   // H reads / W bufs done before next group reuses smem
    }
}

// ===================== launch =====================
extern "C" void kernel_launch(void* const* d_in, const int* in_sizes, int n_in,
                              void* d_out, int out_size)
{
    const float* z     = (const float*)d_in[0];
    const float* sp_W1 = (const float*)d_in[1];
    const float* sp_b1 = (const float*)d_in[2];
    const float* sp_g  = (const float*)d_in[3];
    const float* sp_be = (const float*)d_in[4];
    const float* sp_W2 = (const float*)d_in[5];
    const float* sp_b2 = (const float*)d_in[6];
    const float* kn_W1 = (const float*)d_in[7];
    const float* kn_b1 = (const float*)d_in[8];
    const float* kn_g  = (const float*)d_in[9];
    const float* kn_be = (const float*)d_in[10];
    const float* kn_W2 = (const float*)d_in[11];
    const float* kn_b2 = (const float*)d_in[12];
    const float* de_W1 = (const float*)d_in[13];
    const float* de_b1 = (const float*)d_in[14];
    const float* de_W2 = (const float*)d_in[15];
    const float* de_b2 = (const float*)d_in[16];
    float* out = (float*)d_out;

    long long osz = (long long)out_size;
    int write_n    = (osz >= X_SIZE + B_DIM) ? 1 : 0;
    int write_mask = (osz >= X_SIZE + B_DIM + (long long)B_DIM * MAXN) ? 1 : 0;

    cudaFuncSetAttribute(decoder_kernel,
                         cudaFuncAttributeMaxDynamicSharedMemorySize,
                         DEC_SMEM_BYTES);

    sizepred_kernel<<<512, 256>>>(z, sp_W1, sp_b1, sp_g, sp_be, sp_W2, sp_b2,
                                  out, write_n, write_mask);
    keys_kernel<<<128, 512>>>(kn_W1, kn_b1, kn_g, kn_be, kn_W2, kn_b2);
    prep_kernel<<<1296, 256>>>(de_W1, de_W2);
    decoder_kernel<<<B_DIM, 256, DEC_SMEM_BYTES>>>(z, de_b1, de_b2, out);
}